// round 3
// baseline (speedup 1.0000x reference)
#include <cuda_runtime.h>
#include <math.h>

#define R_TOT 2048   // B*C rows
#define N0 8192
#define M1 4099
#define M2 2053
#define M3 1030
#define M4 518
#define CB 64
#define BB 32

__constant__ float c_dlo[8] = {-0.010597401784997278f, 0.032883011666982945f, 0.030841381835986965f,
                               -0.18703481171888114f, -0.02798376941698385f, 0.6308807679295904f,
                               0.7148465705525415f, 0.23037781330885523f};
__constant__ float c_dhi[8] = {-0.23037781330885523f, 0.7148465705525415f, -0.6308807679295904f,
                               -0.02798376941698385f, 0.18703481171888114f, 0.030841381835986965f,
                               -0.032883011666982945f, -0.010597401784997278f};

// Scratch (static device globals; allocation-free per harness rules)
__device__ float g_xt[(size_t)R_TOT * N0];      // transposed input; reused as y
__device__ float g_d1[(size_t)R_TOT * M1];
__device__ float g_d2[(size_t)R_TOT * M2];
__device__ float g_d3[(size_t)R_TOT * M3];
__device__ float g_a4t[(size_t)M4 * R_TOT];     // [k][row]
__device__ float g_d4t[(size_t)M4 * R_TOT];     // [k][row]
__device__ float g_a4m[(size_t)R_TOT * M4];     // [row][k]
__device__ float g_d4m[(size_t)R_TOT * M4];
__device__ float g_wt1[(size_t)M4 * CB * CB];   // [k][i][o]
__device__ float g_wt2[(size_t)M4 * CB * CB];

// ---------------------------------------------------------------------------
// Transpose: x (B, N, C) -> xt (B*C, N)
// ---------------------------------------------------------------------------
__global__ void transpose_kernel(const float* __restrict__ x, float* __restrict__ xt) {
    __shared__ float tile[32][33];
    int b = blockIdx.z;
    int n0 = blockIdx.x * 32;
    int c0 = blockIdx.y * 32;
    int tx = threadIdx.x, ty = threadIdx.y;  // 32 x 8
#pragma unroll
    for (int i = 0; i < 32; i += 8)
        tile[ty + i][tx] = x[((size_t)b * N0 + n0 + ty + i) * CB + c0 + tx];
    __syncthreads();
#pragma unroll
    for (int i = 0; i < 32; i += 8)
        xt[((size_t)b * CB + c0 + ty + i) * N0 + n0 + tx] = tile[tx][ty + i];
}

// ---------------------------------------------------------------------------
// w (4096, 518) -> wt (518, 4096)   [i*64+o major -> k major]
// ---------------------------------------------------------------------------
__global__ void wtrans_kernel(const float* __restrict__ w1, const float* __restrict__ w2,
                              float* __restrict__ wt1, float* __restrict__ wt2) {
    __shared__ float tile[32][33];
    const float* __restrict__ w  = blockIdx.z ? w2 : w1;
    float* __restrict__       wt = blockIdx.z ? wt2 : wt1;
    int k0 = blockIdx.x * 32;   // col in w (518)
    int r0 = blockIdx.y * 32;   // row in w (4096)
    int tx = threadIdx.x, ty = threadIdx.y;
#pragma unroll
    for (int i = 0; i < 32; i += 8) {
        int kk = k0 + tx;
        if (kk < M4) tile[ty + i][tx] = w[(size_t)(r0 + ty + i) * M4 + kk];
    }
    __syncthreads();
#pragma unroll
    for (int i = 0; i < 32; i += 8) {
        int kk = k0 + ty + i;
        if (kk < M4) wt[(size_t)kk * (CB * CB) + r0 + tx] = tile[tx][ty + i];
    }
}

// ---------------------------------------------------------------------------
// One DWT level from SMEM src (len n) -> SMEM dstA (len m) + gmem dstD
// y[k] = sum_j filt[j] * x_sym[2k+1-j]
// ---------------------------------------------------------------------------
__device__ __forceinline__ void dwt_level_sm(const float* __restrict__ src, int n, int m,
                                             float* __restrict__ dstA, float* __restrict__ dstD) {
    for (int k = threadIdx.x; k < m; k += blockDim.x) {
        int base = 2 * k + 1;
        float sa = 0.f, sd = 0.f;
#pragma unroll
        for (int j = 0; j < 8; j++) {
            int p = base - j;
            p = (p < 0) ? (-1 - p) : p;
            p = (p >= n) ? (2 * n - 1 - p) : p;
            float v = src[p];
            sa = fmaf(v, c_dlo[j], sa);
            sd = fmaf(v, c_dhi[j], sd);
        }
        dstA[k] = sa;
        dstD[k] = sd;
    }
}

// ---------------------------------------------------------------------------
// Fused 4-level DWT: one block per row. x row lives in SMEM the whole time.
// Writes d1/d2/d3 row-major, a4/d4 transposed [k][row] for the mix.
// Dynamic SMEM: 8192 + 4100 floats = 49168 B
// ---------------------------------------------------------------------------
__global__ __launch_bounds__(256) void fused_dwt_kernel(
    const float* __restrict__ xt, float* __restrict__ d1, float* __restrict__ d2,
    float* __restrict__ d3, float* __restrict__ a4t, float* __restrict__ d4t) {
    extern __shared__ float sm[];
    float* sA = sm;          // 8192
    float* sB = sm + N0;     // 4100
    int row = blockIdx.x;
    const float* __restrict__ x = xt + (size_t)row * N0;
    for (int i = threadIdx.x; i < N0; i += blockDim.x) sA[i] = x[i];
    __syncthreads();
    dwt_level_sm(sA, N0, M1, sB, d1 + (size_t)row * M1);   // a1 -> sB
    __syncthreads();
    dwt_level_sm(sB, M1, M2, sA, d2 + (size_t)row * M2);   // a2 -> sA
    __syncthreads();
    dwt_level_sm(sA, M2, M3, sB, d3 + (size_t)row * M3);   // a3 -> sB
    __syncthreads();
    // level 4: write transposed
    for (int k = threadIdx.x; k < M4; k += blockDim.x) {
        int base = 2 * k + 1;
        float sa = 0.f, sd = 0.f;
#pragma unroll
        for (int j = 0; j < 8; j++) {
            int p = base - j;
            p = (p < 0) ? (-1 - p) : p;
            p = (p >= M3) ? (2 * M3 - 1 - p) : p;
            float v = sB[p];
            sa = fmaf(v, c_dlo[j], sa);
            sd = fmaf(v, c_dhi[j], sd);
        }
        a4t[(size_t)k * R_TOT + row] = sa;
        d4t[(size_t)k * R_TOT + row] = sd;
    }
}

// ---------------------------------------------------------------------------
// One IDWT level: A from SMEM (len m), D from gmem (len m) -> out (len out_len)
// p even: taps dec_*[1+2s];  p odd: taps dec_*[2s];  r = p>>1, r+3 < m always.
// ---------------------------------------------------------------------------
__device__ __forceinline__ void idwt_level(const float* __restrict__ A, const float* __restrict__ D,
                                           int m, float* __restrict__ out, int out_len) {
    for (int p = threadIdx.x; p < out_len; p += blockDim.x) {
        int r = p >> 1;
        float s = 0.f;
        if (p & 1) {
#pragma unroll
            for (int t = 0; t < 4; t++)
                s = fmaf(A[r + t], c_dlo[2 * t], fmaf(__ldg(&D[r + t]), c_dhi[2 * t], s));
        } else {
#pragma unroll
            for (int t = 0; t < 4; t++)
                s = fmaf(A[r + t], c_dlo[2 * t + 1], fmaf(__ldg(&D[r + t]), c_dhi[2 * t + 1], s));
        }
        out[p] = s;
    }
}

// ---------------------------------------------------------------------------
// Fused 4-level IDWT: one block per row. Static SMEM 2 x 4100 floats.
// ---------------------------------------------------------------------------
__global__ __launch_bounds__(256) void fused_idwt_kernel(
    const float* __restrict__ a4m, const float* __restrict__ d4m,
    const float* __restrict__ d3, const float* __restrict__ d2,
    const float* __restrict__ d1, float* __restrict__ y) {
    __shared__ float sA[M1 + 1];
    __shared__ float sB[M1 + 1];
    int row = blockIdx.x;
    for (int i = threadIdx.x; i < M4; i += blockDim.x) sB[i] = a4m[(size_t)row * M4 + i];
    __syncthreads();
    idwt_level(sB, d4m + (size_t)row * M4, M4, sA, M3);   // a3 -> sA
    __syncthreads();
    idwt_level(sA, d3 + (size_t)row * M3, M3, sB, M2);    // a2 -> sB
    __syncthreads();
    idwt_level(sB, d2 + (size_t)row * M2, M2, sA, M1);    // a1 -> sA
    __syncthreads();
    // final level straight to gmem (coalesced)
    const float* __restrict__ D = d1 + (size_t)row * M1;
    float* __restrict__ out = y + (size_t)row * N0;
    for (int p = threadIdx.x; p < N0; p += blockDim.x) {
        int r = p >> 1;
        float s = 0.f;
        if (p & 1) {
#pragma unroll
            for (int t = 0; t < 4; t++)
                s = fmaf(sA[r + t], c_dlo[2 * t], fmaf(__ldg(&D[r + t]), c_dhi[2 * t], s));
        } else {
#pragma unroll
            for (int t = 0; t < 4; t++)
                s = fmaf(sA[r + t], c_dlo[2 * t + 1], fmaf(__ldg(&D[r + t]), c_dhi[2 * t + 1], s));
        }
        out[p] = s;
    }
}

// ---------------------------------------------------------------------------
// Channel mix at coarsest level, fully coalesced inputs:
//   in  a4t/d4t [k][row]   (8 KB contiguous per block)
//   wt  [k][i][o]          (16 KB contiguous per block)
//   out a4m/d4m [row][k]   (scattered stores, unavoidable on one side)
// ---------------------------------------------------------------------------
__global__ __launch_bounds__(256) void mix_kernel(
    const float* __restrict__ a4t, const float* __restrict__ d4t,
    const float* __restrict__ wt1, const float* __restrict__ wt2,
    float* __restrict__ a4m, float* __restrict__ d4m) {
    int k = blockIdx.x;
    const float* __restrict__ in = blockIdx.y ? d4t : a4t;
    const float* __restrict__ wt = blockIdx.y ? wt2 : wt1;
    float* __restrict__ out = blockIdx.y ? d4m : a4m;

    __shared__ __align__(16) float ws[4096];  // ws[i*64+o]
    __shared__ float as[32 * 65];             // as[b*65+i]
    int tid = threadIdx.x;
    const float* wk = wt + (size_t)k * 4096;
    const float* ik = in + (size_t)k * R_TOT;
    for (int idx = tid; idx < 4096; idx += 256) ws[idx] = __ldg(&wk[idx]);
    for (int idx = tid; idx < 2048; idx += 256)
        as[(idx >> 6) * 65 + (idx & 63)] = __ldg(&ik[idx]);
    __syncthreads();

    int b = tid >> 3;
    int og = (tid & 7) * 8;
    const float4* ws4 = reinterpret_cast<const float4*>(ws);
    float4 acc0 = make_float4(0.f, 0.f, 0.f, 0.f);
    float4 acc1 = make_float4(0.f, 0.f, 0.f, 0.f);
#pragma unroll
    for (int i = 0; i < 64; i++) {
        float av = as[b * 65 + i];
        float4 w0 = ws4[i * 16 + (og >> 2)];
        float4 wv = ws4[i * 16 + (og >> 2) + 1];
        acc0.x = fmaf(av, w0.x, acc0.x); acc0.y = fmaf(av, w0.y, acc0.y);
        acc0.z = fmaf(av, w0.z, acc0.z); acc0.w = fmaf(av, w0.w, acc0.w);
        acc1.x = fmaf(av, wv.x, acc1.x); acc1.y = fmaf(av, wv.y, acc1.y);
        acc1.z = fmaf(av, wv.z, acc1.z); acc1.w = fmaf(av, wv.w, acc1.w);
    }
    size_t ob = (size_t)(b * 64 + og) * M4 + k;
    out[ob]            = acc0.x; out[ob + (size_t)M4]     = acc0.y;
    out[ob + 2ull*M4]  = acc0.z; out[ob + 3ull*M4]        = acc0.w;
    out[ob + 4ull*M4]  = acc1.x; out[ob + 5ull*M4]        = acc1.y;
    out[ob + 6ull*M4]  = acc1.z; out[ob + 7ull*M4]        = acc1.w;
}

// ---------------------------------------------------------------------------
// Final: out[b,n,c] = mish( y[b*64+c, n] + (x[b,n,:] @ dk)[c] + bias[c] )
// ---------------------------------------------------------------------------
__device__ __forceinline__ float mish_f(float v) {
    float sp = (v > 20.f) ? v : log1pf(expf(v));
    return v * tanhf(sp);
}

__global__ __launch_bounds__(256) void final_kernel(
    const float* __restrict__ y, const float* __restrict__ x,
    const float* __restrict__ dk, const float* __restrict__ bias,
    float* __restrict__ out) {
    int b = blockIdx.y;
    int n0 = blockIdx.x * 32;
    __shared__ __align__(16) float dks[4096];
    __shared__ float xs[32 * 65];
    __shared__ float ys[32 * 65];
    __shared__ float bs[64];
    int tid = threadIdx.x;
    for (int idx = tid; idx < 4096; idx += 256) dks[idx] = __ldg(&dk[idx]);
    if (tid < 64) bs[tid] = __ldg(&bias[tid]);
    for (int idx = tid; idx < 2048; idx += 256) {
        int c = idx >> 5, nn = idx & 31;
        ys[nn * 65 + c] = __ldg(&y[((size_t)b * CB + c) * N0 + n0 + nn]);
    }
    for (int idx = tid; idx < 2048; idx += 256) {
        int nn = idx >> 6, i = idx & 63;
        xs[nn * 65 + i] = __ldg(&x[((size_t)b * N0 + n0 + nn) * CB + i]);
    }
    __syncthreads();

    int nn = tid >> 3;
    int cg = (tid & 7) * 8;
    const float4* dk4 = reinterpret_cast<const float4*>(dks);
    float4 acc0 = make_float4(bs[cg], bs[cg + 1], bs[cg + 2], bs[cg + 3]);
    float4 acc1 = make_float4(bs[cg + 4], bs[cg + 5], bs[cg + 6], bs[cg + 7]);
#pragma unroll
    for (int i = 0; i < 64; i++) {
        float xv = xs[nn * 65 + i];
        float4 w0 = dk4[i * 16 + (cg >> 2)];
        float4 wv = dk4[i * 16 + (cg >> 2) + 1];
        acc0.x = fmaf(xv, w0.x, acc0.x); acc0.y = fmaf(xv, w0.y, acc0.y);
        acc0.z = fmaf(xv, w0.z, acc0.z); acc0.w = fmaf(xv, w0.w, acc0.w);
        acc1.x = fmaf(xv, wv.x, acc1.x); acc1.y = fmaf(xv, wv.y, acc1.y);
        acc1.z = fmaf(xv, wv.z, acc1.z); acc1.w = fmaf(xv, wv.w, acc1.w);
    }
    float vals[8] = {acc0.x, acc0.y, acc0.z, acc0.w, acc1.x, acc1.y, acc1.z, acc1.w};
#pragma unroll
    for (int u = 0; u < 8; u++) {
        float v = vals[u] + ys[nn * 65 + cg + u];
        vals[u] = mish_f(v);
    }
    float4* op = reinterpret_cast<float4*>(&out[((size_t)b * N0 + n0 + nn) * CB + cg]);
    op[0] = make_float4(vals[0], vals[1], vals[2], vals[3]);
    op[1] = make_float4(vals[4], vals[5], vals[6], vals[7]);
}

// ---------------------------------------------------------------------------
extern "C" void kernel_launch(void* const* d_in, const int* in_sizes, int n_in,
                              void* d_out, int out_size) {
    (void)in_sizes; (void)n_in; (void)out_size;
    const float* x    = (const float*)d_in[0];
    const float* w1   = (const float*)d_in[1];
    const float* w2   = (const float*)d_in[2];
    const float* dk   = (const float*)d_in[3];
    const float* bias = (const float*)d_in[4];
    float* out = (float*)d_out;

    float *xt, *d1, *d2, *d3, *a4t, *d4t, *a4m, *d4m, *wt1, *wt2;
    cudaGetSymbolAddress((void**)&xt,  g_xt);
    cudaGetSymbolAddress((void**)&d1,  g_d1);
    cudaGetSymbolAddress((void**)&d2,  g_d2);
    cudaGetSymbolAddress((void**)&d3,  g_d3);
    cudaGetSymbolAddress((void**)&a4t, g_a4t);
    cudaGetSymbolAddress((void**)&d4t, g_d4t);
    cudaGetSymbolAddress((void**)&a4m, g_a4m);
    cudaGetSymbolAddress((void**)&d4m, g_d4m);
    cudaGetSymbolAddress((void**)&wt1, g_wt1);
    cudaGetSymbolAddress((void**)&wt2, g_wt2);

    const int DWT_SMEM = (N0 + M1 + 1) * (int)sizeof(float);  // 49168 B
    cudaFuncSetAttribute(fused_dwt_kernel, cudaFuncAttributeMaxDynamicSharedMemorySize, DWT_SMEM);

    // 1. transpose x -> xt   (independent: w transposes can overlap on same stream order)
    transpose_kernel<<<dim3(N0 / 32, CB / 32, BB), dim3(32, 8)>>>(x, xt);
    // 2. transpose w1/w2 to k-major
    wtrans_kernel<<<dim3((M4 + 31) / 32, (CB * CB) / 32, 2), dim3(32, 8)>>>(w1, w2, wt1, wt2);
    // 3. fused 4-level DWT
    fused_dwt_kernel<<<R_TOT, 256, DWT_SMEM>>>(xt, d1, d2, d3, a4t, d4t);
    // 4. channel mixing (coalesced)
    mix_kernel<<<dim3(M4, 2), 256>>>(a4t, d4t, wt1, wt2, a4m, d4m);
    // 5. fused 4-level IDWT -> y (reuse xt)
    fused_idwt_kernel<<<R_TOT, 256>>>(a4m, d4m, d3, d2, d1, xt);
    // 6. fused transpose-back + dense shortcut + mish
    final_kernel<<<dim3(N0 / 32, BB), 256>>>(xt, x, dk, bias, out);
}

// round 4
// speedup vs baseline: 2.2264x; 2.2264x over previous
#include <cuda_runtime.h>
#include <math.h>

#define R_TOT 2048   // B*C rows
#define N0 8192
#define M1 4099
#define M2 2053
#define M3 1030
#define M4 518
#define CB 64
#define BB 32

__constant__ float c_dlo[8] = {-0.010597401784997278f, 0.032883011666982945f, 0.030841381835986965f,
                               -0.18703481171888114f, -0.02798376941698385f, 0.6308807679295904f,
                               0.7148465705525415f, 0.23037781330885523f};
__constant__ float c_dhi[8] = {-0.23037781330885523f, 0.7148465705525415f, -0.6308807679295904f,
                               -0.02798376941698385f, 0.18703481171888114f, 0.030841381835986965f,
                               -0.032883011666982945f, -0.010597401784997278f};

// Scratch (static device globals; allocation-free per harness rules)
__device__ float g_a1[(size_t)R_TOT * M1];
__device__ float g_d1[(size_t)R_TOT * M1];
__device__ float g_a2[(size_t)R_TOT * M2];
__device__ float g_d2[(size_t)R_TOT * M2];
__device__ float g_a3[(size_t)R_TOT * M3];
__device__ float g_d3[(size_t)R_TOT * M3];
__device__ float g_a4[(size_t)R_TOT * M4];
__device__ float g_d4[(size_t)R_TOT * M4];
__device__ float g_a4t[(size_t)M4 * R_TOT];    // [k][row]
__device__ float g_d4t[(size_t)M4 * R_TOT];
__device__ float g_a4mt[(size_t)M4 * R_TOT];   // mix out, [k][row]
__device__ float g_d4mt[(size_t)M4 * R_TOT];
__device__ float g_a4m[(size_t)R_TOT * M4];    // [row][k]
__device__ float g_d4m[(size_t)R_TOT * M4];
__device__ float g_wt1[(size_t)M4 * CB * CB];  // [k][i*64+o]
__device__ float g_wt2[(size_t)M4 * CB * CB];

// ---------------------------------------------------------------------------
// Generic tiled transpose for a PAIR of arrays: src[R][C] -> dst[C][R]
// ---------------------------------------------------------------------------
__global__ void tr_kernel(const float* __restrict__ s0, const float* __restrict__ s1,
                          float* __restrict__ o0, float* __restrict__ o1, int R, int C) {
    __shared__ float tile[32][33];
    const float* __restrict__ src = blockIdx.z ? s1 : s0;
    float* __restrict__ dst = blockIdx.z ? o1 : o0;
    int c0 = blockIdx.x * 32;
    int r0 = blockIdx.y * 32;
    int tx = threadIdx.x, ty = threadIdx.y;  // 32 x 8
#pragma unroll
    for (int i = 0; i < 32; i += 8) {
        int r = r0 + ty + i, c = c0 + tx;
        if (r < R && c < C) tile[ty + i][tx] = src[(size_t)r * C + c];
    }
    __syncthreads();
#pragma unroll
    for (int i = 0; i < 32; i += 8) {
        int c = c0 + ty + i, r = r0 + tx;
        if (c < C && r < R) dst[(size_t)c * R + r] = tile[tx][ty + i];
    }
}

// ---------------------------------------------------------------------------
// Fused transpose + DWT level 1: reads x (B,N,C) directly.
// Block = (k-tile of 128, (b, c-half)). SMEM tile xs[32 ch][262 samples].
// ---------------------------------------------------------------------------
__global__ __launch_bounds__(256) void dwt1_kernel(const float* __restrict__ x,
                                                   float* __restrict__ a1,
                                                   float* __restrict__ d1) {
    __shared__ float xs[32][263];
    int k0 = blockIdx.x * 128;
    int ct = blockIdx.y;
    int b = ct >> 1;
    int c0 = (ct & 1) * 32;
    int n_start = 2 * k0 - 6;
    for (int idx = threadIdx.x; idx < 262 * 32; idx += 256) {
        int nn = idx >> 5, cc = idx & 31;
        int n = n_start + nn;
        n = (n < 0) ? (-1 - n) : n;
        n = (n >= N0) ? (2 * N0 - 1 - n) : n;
        xs[cc][nn] = __ldg(&x[((size_t)b * N0 + n) * CB + c0 + cc]);
    }
    __syncthreads();
#pragma unroll 4
    for (int s = 0; s < 16; s++) {
        int oi = s * 256 + threadIdx.x;
        int cc = oi >> 7, kk = oi & 127;
        int k = k0 + kk;
        if (k >= M1) continue;
        float sa = 0.f, sd = 0.f;
#pragma unroll
        for (int j = 0; j < 8; j++) {
            float v = xs[cc][2 * kk + 7 - j];
            sa = fmaf(v, c_dlo[j], sa);
            sd = fmaf(v, c_dhi[j], sd);
        }
        size_t off = (size_t)(b * 64 + c0 + cc) * M1 + k;
        a1[off] = sa;
        d1[off] = sd;
    }
}

// ---------------------------------------------------------------------------
// DWT level (2-4): one output per thread, interior fast path (no reflect ALU).
// y[k] = sum_j filt[j] * x_sym[2k+1-j]
// ---------------------------------------------------------------------------
__global__ __launch_bounds__(256) void dwt_kernel(const float* __restrict__ in,
                                                  float* __restrict__ a, float* __restrict__ d,
                                                  int n, int m) {
    int row = blockIdx.y;
    int k = blockIdx.x * 256 + threadIdx.x;
    if (k >= m) return;
    const float* __restrict__ x = in + (size_t)row * n;
    float sa = 0.f, sd = 0.f;
    int base = 2 * k + 1;
    if (base >= 7 && base < n) {
        const float* __restrict__ xp = x + base - 7;
#pragma unroll
        for (int j = 0; j < 8; j++) {
            float v = __ldg(&xp[7 - j]);
            sa = fmaf(v, c_dlo[j], sa);
            sd = fmaf(v, c_dhi[j], sd);
        }
    } else {
#pragma unroll
        for (int j = 0; j < 8; j++) {
            int p = base - j;
            p = (p < 0) ? (-1 - p) : p;
            p = (p >= n) ? (2 * n - 1 - p) : p;
            float v = __ldg(&x[p]);
            sa = fmaf(v, c_dlo[j], sa);
            sd = fmaf(v, c_dhi[j], sd);
        }
    }
    a[(size_t)row * m + k] = sa;
    d[(size_t)row * m + k] = sd;
}

// ---------------------------------------------------------------------------
// IDWT level (4->3, 3->2, 2->1): one thread computes the even/odd output PAIR
// at r=q, sharing the 8 coefficient loads.
// p even: taps filt[1+2t];  p odd: taps filt[2t].  r+3 < m guaranteed.
// ---------------------------------------------------------------------------
__global__ __launch_bounds__(256) void idwt_kernel(const float* __restrict__ ca,
                                                   const float* __restrict__ cd,
                                                   float* __restrict__ out, int m, int out_len) {
    int row = blockIdx.y;
    int q = blockIdx.x * 256 + threadIdx.x;
    int half = (out_len + 1) >> 1;
    if (q >= half) return;
    const float* __restrict__ A = ca + (size_t)row * m + q;
    const float* __restrict__ D = cd + (size_t)row * m + q;
    float se = 0.f, so = 0.f;
#pragma unroll
    for (int t = 0; t < 4; t++) {
        float av = __ldg(&A[t]);
        float dv = __ldg(&D[t]);
        se = fmaf(av, c_dlo[2 * t + 1], fmaf(dv, c_dhi[2 * t + 1], se));
        so = fmaf(av, c_dlo[2 * t],     fmaf(dv, c_dhi[2 * t],     so));
    }
    float* __restrict__ o = out + (size_t)row * out_len + 2 * q;
    o[0] = se;
    if (2 * q + 1 < out_len) o[1] = so;
}

// ---------------------------------------------------------------------------
// Channel mix, all-coalesced: in a4t/d4t [k][row], w [k][i*64+o],
// out [k][row] via float4 stores. Conflict-free LDS mapping:
// thread -> b = tid>>3, o in {g..g+3, g+32..g+35}, g=(tid&7)*4.
// ---------------------------------------------------------------------------
__global__ __launch_bounds__(256) void mix_kernel(
    const float* __restrict__ a4t, const float* __restrict__ d4t,
    const float* __restrict__ wt1, const float* __restrict__ wt2,
    float* __restrict__ a4mt, float* __restrict__ d4mt) {
    int k = blockIdx.x;
    const float* __restrict__ in = blockIdx.y ? d4t : a4t;
    const float* __restrict__ wt = blockIdx.y ? wt2 : wt1;
    float* __restrict__ out = blockIdx.y ? d4mt : a4mt;

    __shared__ __align__(16) float ws[4096];  // ws[i*64+o]
    __shared__ float as[32 * 65];             // as[b*65+i]
    int tid = threadIdx.x;
    const float* __restrict__ wk = wt + (size_t)k * 4096;
    const float* __restrict__ ik = in + (size_t)k * R_TOT;
    for (int idx = tid; idx < 4096; idx += 256) ws[idx] = __ldg(&wk[idx]);
    for (int idx = tid; idx < 2048; idx += 256)
        as[(idx >> 6) * 65 + (idx & 63)] = __ldg(&ik[idx]);
    __syncthreads();

    int b = tid >> 3;
    int lg = tid & 7;  // g = lg*4
    const float4* ws4 = reinterpret_cast<const float4*>(ws);
    float4 acc0 = make_float4(0.f, 0.f, 0.f, 0.f);
    float4 acc1 = make_float4(0.f, 0.f, 0.f, 0.f);
#pragma unroll
    for (int i = 0; i < 64; i++) {
        float av = as[b * 65 + i];
        float4 w0 = ws4[i * 16 + lg];
        float4 w1 = ws4[i * 16 + 8 + lg];
        acc0.x = fmaf(av, w0.x, acc0.x); acc0.y = fmaf(av, w0.y, acc0.y);
        acc0.z = fmaf(av, w0.z, acc0.z); acc0.w = fmaf(av, w0.w, acc0.w);
        acc1.x = fmaf(av, w1.x, acc1.x); acc1.y = fmaf(av, w1.y, acc1.y);
        acc1.z = fmaf(av, w1.z, acc1.z); acc1.w = fmaf(av, w1.w, acc1.w);
    }
    float4* ok = reinterpret_cast<float4*>(out + (size_t)k * R_TOT + b * 64);
    ok[lg] = acc0;
    ok[8 + lg] = acc1;
}

// ---------------------------------------------------------------------------
// Fused IDWT level 1 + transpose-back + dense shortcut + mish.
// Block = (n-tile of 32, b). Reconstructs y[c][n0..n0+31] for all 64 c from
// a1/d1 tiles in SMEM, then out[b,n,c] = mish(y + x@dk + bias).
// ---------------------------------------------------------------------------
__device__ __forceinline__ float mish_f(float v) {
    float sp = (v > 20.f) ? v : log1pf(expf(v));
    return v * tanhf(sp);
}

__global__ __launch_bounds__(256) void ifinal_kernel(
    const float* __restrict__ a1, const float* __restrict__ d1,
    const float* __restrict__ x, const float* __restrict__ dk,
    const float* __restrict__ bias, float* __restrict__ out) {
    int b = blockIdx.y;
    int n0 = blockIdx.x * 32;
    int r0 = n0 >> 1;
    __shared__ float sA[64][20];
    __shared__ float sD[64][20];
    __shared__ __align__(16) float dks[4096];
    __shared__ float xs[32 * 65];
    __shared__ float ys[32 * 65];
    __shared__ float bs[64];
    int tid = threadIdx.x;
    for (int idx = tid; idx < 4096; idx += 256) dks[idx] = __ldg(&dk[idx]);
    if (tid < 64) bs[tid] = __ldg(&bias[tid]);
    for (int idx = tid; idx < 64 * 19; idx += 256) {
        int c = idx / 19, i = idx - c * 19;
        size_t off = (size_t)(b * 64 + c) * M1 + r0 + i;
        sA[c][i] = __ldg(&a1[off]);
        sD[c][i] = __ldg(&d1[off]);
    }
    for (int idx = tid; idx < 2048; idx += 256) {
        int nn = idx >> 6, i = idx & 63;
        xs[nn * 65 + i] = __ldg(&x[((size_t)b * N0 + n0 + nn) * CB + i]);
    }
    __syncthreads();

    // IDWT level 1 into ys[nn][c]
#pragma unroll
    for (int s = 0; s < 8; s++) {
        int oi = s * 256 + tid;
        int c = oi >> 5, nn = oi & 31;
        int ri = nn >> 1;
        float sv = 0.f;
        if (nn & 1) {
#pragma unroll
            for (int t = 0; t < 4; t++)
                sv = fmaf(sA[c][ri + t], c_dlo[2 * t], fmaf(sD[c][ri + t], c_dhi[2 * t], sv));
        } else {
#pragma unroll
            for (int t = 0; t < 4; t++)
                sv = fmaf(sA[c][ri + t], c_dlo[2 * t + 1], fmaf(sD[c][ri + t], c_dhi[2 * t + 1], sv));
        }
        ys[nn * 65 + c] = sv;
    }
    __syncthreads();

    // Dense shortcut + add + mish
    int nn = tid >> 3;
    int lg = tid & 7;
    int g = lg * 4;
    const float4* dk4 = reinterpret_cast<const float4*>(dks);
    float4 acc0 = make_float4(bs[g], bs[g + 1], bs[g + 2], bs[g + 3]);
    float4 acc1 = make_float4(bs[g + 32], bs[g + 33], bs[g + 34], bs[g + 35]);
#pragma unroll
    for (int i = 0; i < 64; i++) {
        float xv = xs[nn * 65 + i];
        float4 w0 = dk4[i * 16 + lg];
        float4 w1 = dk4[i * 16 + 8 + lg];
        acc0.x = fmaf(xv, w0.x, acc0.x); acc0.y = fmaf(xv, w0.y, acc0.y);
        acc0.z = fmaf(xv, w0.z, acc0.z); acc0.w = fmaf(xv, w0.w, acc0.w);
        acc1.x = fmaf(xv, w1.x, acc1.x); acc1.y = fmaf(xv, w1.y, acc1.y);
        acc1.z = fmaf(xv, w1.z, acc1.z); acc1.w = fmaf(xv, w1.w, acc1.w);
    }
    float v0[4] = {acc0.x, acc0.y, acc0.z, acc0.w};
    float v1[4] = {acc1.x, acc1.y, acc1.z, acc1.w};
#pragma unroll
    for (int u = 0; u < 4; u++) {
        v0[u] = mish_f(v0[u] + ys[nn * 65 + g + u]);
        v1[u] = mish_f(v1[u] + ys[nn * 65 + g + 32 + u]);
    }
    float4* op = reinterpret_cast<float4*>(&out[((size_t)b * N0 + n0 + nn) * CB]);
    op[lg] = make_float4(v0[0], v0[1], v0[2], v0[3]);
    op[8 + lg] = make_float4(v1[0], v1[1], v1[2], v1[3]);
}

// ---------------------------------------------------------------------------
extern "C" void kernel_launch(void* const* d_in, const int* in_sizes, int n_in,
                              void* d_out, int out_size) {
    (void)in_sizes; (void)n_in; (void)out_size;
    const float* x    = (const float*)d_in[0];
    const float* w1   = (const float*)d_in[1];
    const float* w2   = (const float*)d_in[2];
    const float* dk   = (const float*)d_in[3];
    const float* bias = (const float*)d_in[4];
    float* out = (float*)d_out;

    float *a1, *d1, *a2, *d2, *a3, *d3, *a4, *d4;
    float *a4t, *d4t, *a4mt, *d4mt, *a4m, *d4m, *wt1, *wt2;
    cudaGetSymbolAddress((void**)&a1,   g_a1);
    cudaGetSymbolAddress((void**)&d1,   g_d1);
    cudaGetSymbolAddress((void**)&a2,   g_a2);
    cudaGetSymbolAddress((void**)&d2,   g_d2);
    cudaGetSymbolAddress((void**)&a3,   g_a3);
    cudaGetSymbolAddress((void**)&d3,   g_d3);
    cudaGetSymbolAddress((void**)&a4,   g_a4);
    cudaGetSymbolAddress((void**)&d4,   g_d4);
    cudaGetSymbolAddress((void**)&a4t,  g_a4t);
    cudaGetSymbolAddress((void**)&d4t,  g_d4t);
    cudaGetSymbolAddress((void**)&a4mt, g_a4mt);
    cudaGetSymbolAddress((void**)&d4mt, g_d4mt);
    cudaGetSymbolAddress((void**)&a4m,  g_a4m);
    cudaGetSymbolAddress((void**)&d4m,  g_d4m);
    cudaGetSymbolAddress((void**)&wt1,  g_wt1);
    cudaGetSymbolAddress((void**)&wt2,  g_wt2);

    dim3 trb(32, 8);
    // 1. fused transpose + DWT L1 (reads x directly)
    dwt1_kernel<<<dim3((M1 + 127) / 128, BB * 2), 256>>>(x, a1, d1);
    // 2-4. DWT levels 2-4 (split, massively parallel)
    dwt_kernel<<<dim3((M2 + 255) / 256, R_TOT), 256>>>(a1, a2, d2, M1, M2);
    dwt_kernel<<<dim3((M3 + 255) / 256, R_TOT), 256>>>(a2, a3, d3, M2, M3);
    dwt_kernel<<<dim3((M4 + 255) / 256, R_TOT), 256>>>(a3, a4, d4, M3, M4);
    // 5. transpose a4,d4 -> k-major; 6. transpose weights -> k-major
    tr_kernel<<<dim3((M4 + 31) / 32, R_TOT / 32, 2), trb>>>(a4, d4, a4t, d4t, R_TOT, M4);
    tr_kernel<<<dim3((M4 + 31) / 32, (CB * CB) / 32, 2), trb>>>(w1, w2, wt1, wt2, CB * CB, M4);
    // 7. channel mix (fully coalesced)
    mix_kernel<<<dim3(M4, 2), 256>>>(a4t, d4t, wt1, wt2, a4mt, d4mt);
    // 8. transpose mixed back to row-major
    tr_kernel<<<dim3(R_TOT / 32, (M4 + 31) / 32, 2), trb>>>(a4mt, d4mt, a4m, d4m, M4, R_TOT);
    // 9-11. IDWT levels 4->3->2->1 (split, pair-per-thread)
    idwt_kernel<<<dim3((((M3 + 1) / 2) + 255) / 256, R_TOT), 256>>>(a4m, d4m, a3, M4, M3);
    idwt_kernel<<<dim3((((M2 + 1) / 2) + 255) / 256, R_TOT), 256>>>(a3, d3, a2, M3, M2);
    idwt_kernel<<<dim3((((M1 + 1) / 2) + 255) / 256, R_TOT), 256>>>(a2, d2, a1, M2, M1);
    // 12. fused IDWT L1 + transpose-back + dense shortcut + mish
    ifinal_kernel<<<dim3(N0 / 32, BB), 256>>>(a1, d1, x, dk, bias, out);
}